// round 8
// baseline (speedup 1.0000x reference)
#include <cuda_runtime.h>
#include <cstdint>

#define M_PTS 5151
#define HIDN  256
#define BB    16
#define SS    256
#define TT    1024
#define GRID_N 101
#define TDIM   16
#define NTILES 28
#define TC     32
#define TSTR   36
#define CUT 0.018f

#define OFF_BOUT 0
#define OFF_D    16384
#define OFF_M    (OFF_D + BB*M_PTS)
#define OFF_IS   (OFF_M + BB*TT)
#define OFF_MESH (OFF_IS + BB*M_PTS)

// ---------------- scratch ----------------
__device__ float g_x[5248*HIDN];
__device__ float g_y[5248*HIDN];
__device__ float g_xhi[5248*HIDN];
__device__ float g_xlo[5248*HIDN];
__device__ float g_yhi[5248*HIDN];
__device__ float g_ylo[5248*HIDN];
__device__ float g_whi[3*HIDN*HIDN];
__device__ float g_wlo[3*HIDN*HIDN];
__device__ float g_density[M_PTS];
__device__ float g_cwc[BB*HIDN];
__device__ float g_init[BB*M_PTS];
__device__ float g_bpart[BB*NTILES*TT];

__device__ __forceinline__ float fast_tanh(float x) {
    float r;
    asm("tanh.approx.f32 %0, %1;" : "=f"(r) : "f"(x));
    return r;
}

__device__ __forceinline__ float to_tf32(float x) {
    uint32_t r;
    asm("cvt.rna.tf32.f32 %0, %1;" : "=r"(r) : "f"(x));
    return __uint_as_float(r);
}

__device__ __forceinline__ void mma_tf32(float* c, const float* a, const float* b) {
    asm volatile(
        "mma.sync.aligned.m16n8k8.row.col.f32.tf32.tf32.f32 "
        "{%0,%1,%2,%3}, {%4,%5,%6,%7}, {%8,%9}, {%0,%1,%2,%3};"
        : "+f"(c[0]), "+f"(c[1]), "+f"(c[2]), "+f"(c[3])
        : "r"(__float_as_uint(a[0])), "r"(__float_as_uint(a[1])),
          "r"(__float_as_uint(a[2])), "r"(__float_as_uint(a[3])),
          "r"(__float_as_uint(b[0])), "r"(__float_as_uint(b[1])));
}

// ---------------- W split (once) ----------------
__global__ void k_wsplit(const float* __restrict__ Wr) {
    int i = blockIdx.x*256 + threadIdx.x;
    if (i >= 3*HIDN*HIDN) return;
    float w = Wr[i];
    float hi = to_tf32(w);
    g_whi[i] = hi;
    g_wlo[i] = to_tf32(w - hi);
}

// ---------------- density input layer ----------------
__global__ void k_dens_in(const float* __restrict__ mesh,
                          const float* __restrict__ Win,
                          const float* __restrict__ bin) {
    int m = blockIdx.x;
    int j = threadIdx.x;
    float be = mesh[2*m], al = mesh[2*m+1];
    float v = fmaxf(be*Win[j] + al*Win[HIDN+j] + bin[j], 0.f);
    g_x[m*HIDN + j] = v;
    float hi = to_tf32(v);
    g_xhi[m*HIDN + j] = hi;
    g_xlo[m*HIDN + j] = to_tf32(v - hi);
}

// ---------------- residual layer via 3xTF32 mma ----------------
// 64x64 tile, 256 thr, 8 warps (warp = 16 rows x 32 cols), BK=32.
__global__ void __launch_bounds__(256) k_res_tc(const float* __restrict__ bias,
                                                int flip, int layer) {
    const float* Xf  = flip ? g_y   : g_x;
    const float* Xhi = flip ? g_yhi : g_xhi;
    const float* Xlo = flip ? g_ylo : g_xlo;
    float* Yf  = flip ? g_x   : g_y;
    float* Yhi = flip ? g_xhi : g_yhi;
    float* Ylo = flip ? g_xlo : g_ylo;
    const float* Whi = g_whi + layer*HIDN*HIDN;
    const float* Wlo = g_wlo + layer*HIDN*HIDN;

    __shared__ __align__(16) float Ah[64][36];
    __shared__ __align__(16) float Al[64][36];
    __shared__ __align__(16) float Bh[32][72];
    __shared__ __align__(16) float Bl[32][72];

    int bm = blockIdx.x*64, bn = blockIdx.y*64;
    int tid = threadIdx.x;
    int warp = tid >> 5, lane = tid & 31;
    int lr = lane >> 2, lc = lane & 3;
    int m_base = (warp >> 1) * 16;
    int n_base = (warp & 1) * 32;

    float acc[4][4];
#pragma unroll
    for (int j = 0; j < 4; j++)
#pragma unroll
        for (int q = 0; q < 4; q++) acc[j][q] = 0.f;

    const float4 z4 = make_float4(0.f,0.f,0.f,0.f);

    for (int k0 = 0; k0 < HIDN; k0 += 32) {
        __syncthreads();
        // stage A: 64 rows x 32 k (hi+lo). 512 float4 per array, 2/thread.
#pragma unroll
        for (int u = 0; u < 2; u++) {
            int i = tid + u*256;
            int row = i >> 3, c4 = (i & 7) * 4;
            int gr = bm + row;
            bool ok = gr < M_PTS;
            size_t g = (size_t)(ok ? gr : 0)*HIDN + k0 + c4;
            float4 vh = ok ? *(const float4*)&Xhi[g] : z4;
            float4 vl = ok ? *(const float4*)&Xlo[g] : z4;
            *(float4*)&Ah[row][c4] = vh;
            *(float4*)&Al[row][c4] = vl;
        }
        // stage B: 32 k x 64 n (hi+lo). 512 float4 per array, 2/thread.
#pragma unroll
        for (int u = 0; u < 2; u++) {
            int i = tid + u*256;
            int kr = i >> 4, c4 = (i & 15) * 4;
            size_t g = (size_t)(k0 + kr)*HIDN + bn + c4;
            *(float4*)&Bh[kr][c4] = *(const float4*)&Whi[g];
            *(float4*)&Bl[kr][c4] = *(const float4*)&Wlo[g];
        }
        __syncthreads();

#pragma unroll
        for (int kk = 0; kk < 32; kk += 8) {
            float ah[4], al[4];
            ah[0] = Ah[m_base + lr    ][kk + lc];
            ah[1] = Ah[m_base + lr + 8][kk + lc];
            ah[2] = Ah[m_base + lr    ][kk + lc + 4];
            ah[3] = Ah[m_base + lr + 8][kk + lc + 4];
            al[0] = Al[m_base + lr    ][kk + lc];
            al[1] = Al[m_base + lr + 8][kk + lc];
            al[2] = Al[m_base + lr    ][kk + lc + 4];
            al[3] = Al[m_base + lr + 8][kk + lc + 4];
#pragma unroll
            for (int j = 0; j < 4; j++) {
                int n = n_base + j*8 + lr;
                float bh[2], bl[2];
                bh[0] = Bh[kk + lc    ][n];
                bh[1] = Bh[kk + lc + 4][n];
                bl[0] = Bl[kk + lc    ][n];
                bl[1] = Bl[kk + lc + 4][n];
                mma_tf32(acc[j], ah, bh);
                mma_tf32(acc[j], ah, bl);
                mma_tf32(acc[j], al, bh);
            }
        }
    }

    // epilogue: Y = X + relu(acc + bias); also emit tf32 split of Y
    int r0 = bm + m_base + lr;
    int r1 = r0 + 8;
#pragma unroll
    for (int j = 0; j < 4; j++) {
        int c = bn + n_base + j*8 + 2*lc;
        float2 bz = *(const float2*)&bias[c];
#pragma unroll
        for (int h = 0; h < 2; h++) {
            int r = h ? r1 : r0;
            if (r >= M_PTS) continue;
            float v0 = acc[j][h*2 + 0] + bz.x;
            float v1 = acc[j][h*2 + 1] + bz.y;
            size_t g = (size_t)r*HIDN + c;
            float2 xv = *(const float2*)&Xf[g];
            float y0 = xv.x + fmaxf(v0, 0.f);
            float y1 = xv.y + fmaxf(v1, 0.f);
            *(float2*)&Yf[g] = make_float2(y0, y1);
            float h0 = to_tf32(y0), h1 = to_tf32(y1);
            *(float2*)&Yhi[g] = make_float2(h0, h1);
            *(float2*)&Ylo[g] = make_float2(to_tf32(y0 - h0), to_tf32(y1 - h1));
        }
    }
}

// ---------------- density output ----------------
__global__ void k_dens_out(const float* __restrict__ Wout,
                           const float* __restrict__ bout) {
    int w = blockIdx.x*8 + (threadIdx.x >> 5);
    int lane = threadIdx.x & 31;
    if (w >= M_PTS) return;
    float acc = 0.f;
#pragma unroll
    for (int i = 0; i < 8; i++)
        acc += g_y[w*HIDN + lane + i*32] * Wout[lane + i*32];
#pragma unroll
    for (int o = 16; o; o >>= 1) acc += __shfl_xor_sync(0xffffffffu, acc, o);
    if (lane == 0) {
        float z = acc + bout[0];
        g_density[w] = 1.f / (1.f + __expf(-z));
    }
}

// ---------------- encoder ctx + ctx @ Wc ----------------
__global__ void k_ctxw(const float* __restrict__ enc,
                       const float* __restrict__ mask,
                       const float* __restrict__ Ws,
                       const float* __restrict__ bs,
                       const float* __restrict__ Wc) {
    int b = blockIdx.x;
    int j = threadIdx.x;
    __shared__ float se[2*SS];
    __shared__ float sm[SS];
    __shared__ float sctx[HIDN];
    for (int i = j; i < 2*SS; i += 256) se[i] = enc[b*2*SS + i];
    for (int i = j; i < SS;   i += 256) sm[i] = mask[b*SS + i];
    __syncthreads();
    float w0 = Ws[j], w1 = Ws[HIDN + j], bj = bs[j];
    float acc = 0.f, msum = 0.f;
    for (int s = 0; s < SS; s++) {
        float mk = sm[s];
        msum += mk;
        float v = fmaxf(se[2*s]*w0 + se[2*s+1]*w1 + bj, 0.f);
        acc += mk * v;
    }
    sctx[j] = acc / fmaxf(msum, 1.f);
    __syncthreads();
    float a2 = 0.f;
    for (int k = 0; k < HIDN; k++) a2 += sctx[k] * Wc[k*HIDN + j];
    g_cwc[b*HIDN + j] = a2;
}

// ------- initial states + density/mesh replication -------
__global__ void k_init(const float* __restrict__ mesh,
                       const float* __restrict__ Wm,
                       const float* __restrict__ bm,
                       const float* __restrict__ Wo,
                       const float* __restrict__ bo,
                       float* __restrict__ out) {
    int b = blockIdx.y;
    int j = threadIdx.x;
    __shared__ __align__(16) float sW0[HIDN], sW1[HIDN], sW2[HIDN], sWo[HIDN], sC[HIDN];
    sW0[j] = Wm[j];
    sW1[j] = Wm[HIDN + j];
    sW2[j] = Wm[2*HIDN + j];
    sWo[j] = Wo[j];
    sC[j]  = g_cwc[b*HIDN + j] + bm[j];
    __syncthreads();

    int m[4]; bool v[4];
    float be[4], al[4], d[4], acc[4];
#pragma unroll
    for (int q = 0; q < 4; q++) {
        m[q] = blockIdx.x*1024 + q*256 + j;
        v[q] = m[q] < M_PTS;
        int mm = v[q] ? m[q] : 0;
        be[q] = mesh[2*mm];
        al[q] = mesh[2*mm + 1];
        d[q]  = g_density[mm];
        acc[q] = 0.f;
    }

    const float4* w0 = (const float4*)sW0;
    const float4* w1 = (const float4*)sW1;
    const float4* w2 = (const float4*)sW2;
    const float4* wo = (const float4*)sWo;
    const float4* cc = (const float4*)sC;
#pragma unroll 2
    for (int qq = 0; qq < HIDN/4; qq++) {
        float4 a0 = w0[qq], a1 = w1[qq], a2 = w2[qq], ao = wo[qq], ac = cc[qq];
#pragma unroll
        for (int q = 0; q < 4; q++) {
            acc[q] += fmaxf(ac.x + be[q]*a0.x + al[q]*a1.x + d[q]*a2.x, 0.f) * ao.x;
            acc[q] += fmaxf(ac.y + be[q]*a0.y + al[q]*a1.y + d[q]*a2.y, 0.f) * ao.y;
            acc[q] += fmaxf(ac.z + be[q]*a0.z + al[q]*a1.z + d[q]*a2.z, 0.f) * ao.z;
            acc[q] += fmaxf(ac.w + be[q]*a0.w + al[q]*a1.w + d[q]*a2.w, 0.f) * ao.w;
        }
    }
    float bo0 = bo[0];
#pragma unroll
    for (int q = 0; q < 4; q++) {
        if (!v[q]) continue;
        float is = tanhf(acc[q] + bo0);
        g_init[b*M_PTS + m[q]] = is;
        out[OFF_IS + (size_t)b*M_PTS + m[q]] = is;
        out[OFF_D  + (size_t)b*M_PTS + m[q]] = d[q];
        ((float2*)out)[(OFF_MESH >> 1) + (size_t)b*M_PTS + m[q]] = make_float2(be[q], al[q]);
    }
}

// ------- relay scan: 2D triangle tiles, 256 thr -------
__global__ void __launch_bounds__(256) k_scan(const float* __restrict__ dec,
                                              const float* __restrict__ mesh) {
    __shared__ __align__(16) float sh_h[TT];
    __shared__ __align__(16) float tile[256*TSTR];
    __shared__ float aux[8][TC];
    int b = blockIdx.y;
    int tid = threadIdx.x;

    int tile_id = blockIdx.x;
    int tb = 0, rem = tile_id;
    while (rem >= 7 - tb) { rem -= 7 - tb; tb++; }
    int ta = tb + rem;

    int ib = tb*TDIM + (tid >> 4);
    int ia = ta*TDIM + (tid & 15);
    bool valid = (ib < GRID_N) && (ia < GRID_N) && (ia >= ib);
    int idx = 0;
    if (valid) idx = ib*GRID_N - (ib*(ib-1))/2 + (ia - ib);

    for (int t = tid; t < TT; t += 256) sh_h[t] = dec[b*TT + t];

    float be = valid ? mesh[2*idx]     : -2.f;
    float al = valid ? mesh[2*idx + 1] :  2.f;
    float d  = valid ? g_density[idx]  :  0.f;
    float sg = valid ? d * g_init[b*M_PTS + idx] : 0.f;
    float nd = -d;
    __syncthreads();

    float* myrow = &tile[tid*TSTR];
    int rcol  = tid & (TC-1);
    int rbase = (tid >> 5) * 32;
    float* gout = &g_bpart[((size_t)b*NTILES + blockIdx.x)*TT];

    for (int c0 = 0; c0 < TT; c0 += TC) {
#pragma unroll 2
        for (int t4 = 0; t4 < TC; t4 += 4) {
            float4 h4 = *(const float4*)&sh_h[c0 + t4];
            float o[4];
            float hts[4] = {h4.x, h4.y, h4.z, h4.w};
#pragma unroll
            for (int u = 0; u < 4; u++) {
                float ht = hts[u];
                float xu = ht - al;
                float xd = be - ht;
                bool nearany = (fabsf(xu) < CUT) | (fabsf(xd) < CUT);
                if (__any_sync(0xffffffffu, nearany)) {
                    float wu = 0.5f*fast_tanh(500.f*xu) + 0.5f;
                    float wd = 0.5f*fast_tanh(500.f*xd) + 0.5f;
                    sg += wu * (d  - sg);
                    sg += wd * (nd - sg);
                } else {
                    if (xu > 0.f) sg = d;
                    if (xd > 0.f) sg = nd;
                }
                o[u] = sg;
            }
            *(float4*)&myrow[t4] = make_float4(o[0], o[1], o[2], o[3]);
        }
        __syncthreads();
        float a = 0.f;
#pragma unroll 8
        for (int i = 0; i < 32; i++)
            a += tile[(rbase + i)*TSTR + rcol];
        aux[tid >> 5][rcol] = a;
        __syncthreads();
        if (tid < TC) {
            float g = 0.f;
#pragma unroll
            for (int w = 0; w < 8; w++) g += aux[w][tid];
            gout[c0 + tid] = g;
        }
        __syncthreads();
    }
}

// ---------------- final ----------------
__global__ void k_final(const float* __restrict__ dec,
                        const float* __restrict__ hraw,
                        const float* __restrict__ mraw,
                        const float* __restrict__ oraw,
                        float* __restrict__ out) {
    __shared__ float sred[256];
    int tid = threadIdx.x;
    float a = 0.f;
    for (int i = tid; i < M_PTS; i += 256) a += g_density[i];
    sred[tid] = a;
    __syncthreads();
    for (int o = 128; o; o >>= 1) {
        if (tid < o) sred[tid] += sred[tid + o];
        __syncthreads();
    }
    float dsum = sred[0];

    int i = blockIdx.x*256 + tid;
    int b = i >> 10, t = i & 1023;
    float acc = 0.f;
#pragma unroll
    for (int k = 0; k < NTILES; k++)
        acc += g_bpart[((size_t)b*NTILES + k)*TT + t];
    float mv = acc / dsum;
    float h = dec[i];
    float hs  = 10.f / (1.f + __expf(-hraw[0]));
    float ms  = 10.f / (1.f + __expf(-mraw[0]));
    float off = -10.f + 20.f / (1.f + __expf(-oraw[0]));
    out[OFF_BOUT + i] = hs*h + ms*mv + off;
    out[OFF_M + i] = mv;
}

// ---------------- launch ----------------
extern "C" void kernel_launch(void* const* d_in, const int* in_sizes, int n_in,
                              void* d_out, int out_size) {
    (void)in_sizes; (void)n_in; (void)out_size;
    const float* enc   = (const float*)d_in[0];
    const float* dec   = (const float*)d_in[1];
    const float* msk   = (const float*)d_in[2];
    const float* mesh  = (const float*)d_in[3];
    const float* dWin  = (const float*)d_in[4];
    const float* dbin  = (const float*)d_in[5];
    const float* dWr   = (const float*)d_in[6];
    const float* dbr   = (const float*)d_in[7];
    const float* dWout = (const float*)d_in[8];
    const float* dbout = (const float*)d_in[9];
    const float* eWs   = (const float*)d_in[10];
    const float* ebs   = (const float*)d_in[11];
    const float* eWm   = (const float*)d_in[12];
    const float* eWc   = (const float*)d_in[13];
    const float* ebm   = (const float*)d_in[14];
    const float* eWo   = (const float*)d_in[15];
    const float* ebo   = (const float*)d_in[16];
    const float* hraw  = (const float*)d_in[17];
    const float* mraw  = (const float*)d_in[18];
    const float* oraw  = (const float*)d_in[19];
    float* out = (float*)d_out;

    // density MLP (tensor path)
    k_wsplit<<<768, 256>>>(dWr);
    k_dens_in<<<M_PTS, 256>>>(mesh, dWin, dbin);
    dim3 gres(81, 4);
    k_res_tc<<<gres, 256>>>(dbr + 0*HIDN, 0, 0);  // x -> y
    k_res_tc<<<gres, 256>>>(dbr + 1*HIDN, 1, 1);  // y -> x
    k_res_tc<<<gres, 256>>>(dbr + 2*HIDN, 0, 2);  // x -> y
    k_dens_out<<<644, 256>>>(dWout, dbout);

    // encoder + initial states
    k_ctxw<<<BB, 256>>>(enc, msk, eWs, ebs, eWc);
    dim3 ginit(6, BB);
    k_init<<<ginit, 256>>>(mesh, eWm, ebm, eWo, ebo, out);

    // relay scan + final
    dim3 gscan(NTILES, BB);
    k_scan<<<gscan, 256>>>(dec, mesh);
    k_final<<<64, 256>>>(dec, hraw, mraw, oraw, out);
}